// round 2
// baseline (speedup 1.0000x reference)
#include <cuda_runtime.h>
#include <math.h>

#define Bb 8
#define NPTS 20000
#define PP 256
#define SS 32
#define CC 256
#define NCLS 18

// ---- output layout (concatenated float32) ----
// r0 new_xyz      [B,P,3]    off 0      size 6144
// r1 new_features [B,128,P]  off 6144   size 262144
// r2 label_feature[B,256,P]  off 268288 size 524288
// r3 inds (float) [B,P]      off 792576 size 2048
#define OFF_NF   6144
#define OFF_LAB  268288
#define OFF_INDS 792576

// ---- scratch (__device__ globals; no allocation allowed) ----
__device__ float d_sin128[Bb*128];
__device__ float d_sin256[Bb*256];
__device__ float d_h512[Bb*512];
__device__ float d_temb512[Bb*512];
__device__ float d_ss256[Bb*256];
__device__ float d_h1024[Bb*1024];
__device__ float d_temb1024[Bb*1024];
__device__ float d_ss512[Bb*512];
__device__ int   d_samp[Bb*PP*SS];
__device__ float d_center[Bb*PP*3];
__device__ float d_nf[Bb*PP*128];
// vectorized transposed weights: layout [(c4*O + o)*4 + j] = W[o][c4*4+j] (0-padded)
__device__ float d_w0v[65*128*4];
__device__ float d_w1v[32*128*4];
__device__ float d_w2v[32*128*4];
__device__ float d_l0v[37*256*4];
__device__ float d_l1v[64*256*4];
__device__ float d_l2v[64*256*4];

__device__ __forceinline__ float* buf_ptr(int id) {
    switch (id) {
        case 0: return d_sin128;   case 1: return d_sin256;
        case 2: return d_h512;     case 3: return d_temb512;
        case 4: return d_ss256;    case 5: return d_h1024;
        case 6: return d_temb1024; case 7: return d_ss512;
        case 10: return d_w0v;  case 11: return d_w1v;  case 12: return d_w2v;
        case 13: return d_l0v;  case 14: return d_l1v;  case 15: return d_l2v;
    }
    return nullptr;
}

// ---- weight transpose to vectorized layout ----
__global__ void k_transpose_vec(const float* __restrict__ W, int dst_id,
                                int O, int Cin, int C4) {
    int i = blockIdx.x * blockDim.x + threadIdx.x;
    int total = C4 * O * 4;
    if (i >= total) return;
    int j  = i & 3;
    int r  = i >> 2;
    int o  = r % O;
    int c4 = r / O;
    int c  = c4 * 4 + j;
    buf_ptr(dst_id)[i] = (c < Cin) ? W[o * Cin + c] : 0.f;
}

// ---- sinusoidal embeddings (double-precision trig: safe vs fast-math) ----
__global__ void k_sinusoid(const float* __restrict__ ts) {
    int i = blockIdx.x * blockDim.x + threadIdx.x;
    if (i < Bb * 128) {
        int b = i >> 7, j = i & 127;
        int k = (j < 64) ? j : j - 64;
        float fr = expf((float)k * (float)(-9.210340371976184 / 63.0));
        float e = ts[b] * fr;
        d_sin128[i] = (float)((j < 64) ? sin((double)e) : cos((double)e));
    } else if (i < Bb * 128 + Bb * 256) {
        int ii = i - Bb * 128;
        int b = ii >> 8, j = ii & 255;
        int k = (j < 128) ? j : j - 128;
        float fr = expf((float)k * (float)(-9.210340371976184 / 127.0));
        float e = ts[b] * fr;
        d_sin256[ii] = (float)((j < 128) ? sin((double)e) : cos((double)e));
    }
}

__device__ __forceinline__ float gelu_exact(float x) {
    return 0.5f * x * (1.0f + erff(x * 0.70710678118654752f));
}
__device__ __forceinline__ float silu_f(float x) {
    return x / (1.0f + expf(-x));
}

// ---- small dense layer: out[b][o] = sum_i act(in[b][i]) * W[o][i] + bias[o] ----
__global__ void k_dense(int in_id, const float* __restrict__ W,
                        const float* __restrict__ bias, int out_id,
                        int I, int O, int act) {
    int g = blockIdx.x * blockDim.x + threadIdx.x;
    if (g >= Bb * O) return;
    int b = g / O, o = g % O;
    const float* ib = buf_ptr(in_id) + b * I;
    const float* wr = W + (size_t)o * I;
    float acc = bias[o];
    for (int i = 0; i < I; i++) {
        float v = ib[i];
        if (act == 1) v = gelu_exact(v);
        else if (act == 2) v = silu_f(v);
        acc = fmaf(v, wr[i], acc);
    }
    buf_ptr(out_id)[g] = acc;
}

// ---- per-(b,p) warp: box containment + ordered cyclic sampling ----
__global__ void k_select(const float* __restrict__ xyz,
                         const float* __restrict__ bsize,
                         const int* __restrict__ inds,
                         float* __restrict__ out) {
    int warp = (blockIdx.x * blockDim.x + threadIdx.x) >> 5;
    int lane = threadIdx.x & 31;
    int wloc = threadIdx.x >> 5;
    __shared__ int buf[8][SS];
    if (warp >= Bb * PP) return;
    int b = warp / PP;

    int ind = inds[warp];
    const float* cp = xyz + ((size_t)b * NPTS + ind) * 3;
    float cx = cp[0], cy = cp[1], cz = cp[2];
    float hx = bsize[warp * 3 + 0] * 0.5f;
    float hy = bsize[warp * 3 + 1] * 0.5f;
    float hz = bsize[warp * 3 + 2] * 0.5f;

    int found = 0;
    for (int base = 0; base < NPTS; base += 32) {
        int i = base + lane;
        const float* pt = xyz + ((size_t)b * NPTS + i) * 3;
        float x = pt[0], y = pt[1], z = pt[2];
        bool in = (fabsf(x - cx) <= hx) && (fabsf(y - cy) <= hy) && (fabsf(z - cz) <= hz);
        unsigned m = __ballot_sync(0xffffffffu, in);
        if (in) {
            int r = found + __popc(m & ((1u << lane) - 1u));
            if (r < SS) buf[wloc][r] = i;
        }
        found += __popc(m);
        if (found >= SS) break;
    }
    int ce = found < SS ? found : SS;
    if (ce == 0) { if (lane == 0) buf[wloc][0] = 0; ce = 1; }  // unreachable: center is in-box
    __syncwarp();
    d_samp[warp * SS + lane] = buf[wloc][lane % ce];

    if (lane < 3) {
        float cv = (lane == 0) ? cx : ((lane == 1) ? cy : cz);
        out[warp * 3 + lane] = cv;
        d_center[warp * 3 + lane] = cv;
    }
    if (lane == 0) out[OFF_INDS + warp] = (float)ind;
}

// ---- point MLP: gather g=[xyz_rel|feat] -> 3x dense+relu -> maxpool -> FiLM ----
// Static smem only (33.4 KB): hidden buffers ping-pong inside the g staging
// region (8320 floats >= 2 x 4096), so no dynamic-smem attribute is needed.
__global__ void __launch_bounds__(128)
k_pointmlp(const float* __restrict__ xyz, const float* __restrict__ feat,
           const float* __restrict__ mb0, const float* __restrict__ mb1,
           const float* __restrict__ mb2, float* __restrict__ out) {
    int bp = blockIdx.x;
    int b = bp >> 8, p = bp & 255;
    int t = threadIdx.x;
    __shared__ __align__(16) float g[32 * 260];   // staging, then h ping-pong
    __shared__ int sidx[SS];
    __shared__ float ctr[3];
    if (t < SS) sidx[t] = d_samp[bp * SS + t];
    if (t < 3)  ctr[t]  = d_center[bp * 3 + t];
    __syncthreads();
    if (t < 96) {
        int s = t / 3, d = t % 3;
        g[s * 260 + d] = xyz[((size_t)b * NPTS + sidx[s]) * 3 + d] - ctr[d];
    }
    if (t < SS) g[t * 260 + 259] = 0.f;
    const float* fb = feat + (size_t)b * CC * NPTS;
    for (int it = 0; it < 64; it++) {
        int e = it * 128 + t;
        int s = e >> 8, c = e & 255;
        g[s * 260 + 3 + c] = fb[(size_t)c * NPTS + sidx[s]];
    }
    __syncthreads();

    float acc[SS];
    // layer 0: 259 -> 128 (reads all of g; output held in regs until sync)
    {
        float bv = mb0[t];
        #pragma unroll
        for (int s = 0; s < SS; s++) acc[s] = bv;
        const float4* wv = (const float4*)d_w0v;
        for (int c4 = 0; c4 < 65; c4++) {
            float4 w = wv[c4 * 128 + t];
            #pragma unroll
            for (int s = 0; s < SS; s++) {
                float4 gv = *(const float4*)(g + s * 260 + c4 * 4);
                acc[s] = fmaf(gv.x, w.x, acc[s]);
                acc[s] = fmaf(gv.y, w.y, acc[s]);
                acc[s] = fmaf(gv.z, w.z, acc[s]);
                acc[s] = fmaf(gv.w, w.w, acc[s]);
            }
        }
    }
    __syncthreads();                      // everyone done reading g
    float* h0 = g;                        // [32][128] at offset 0
    float* h1 = g + 32 * 128;             // [32][128] at offset 4096
    #pragma unroll
    for (int s = 0; s < SS; s++) h0[s * 128 + t] = fmaxf(acc[s], 0.f);
    __syncthreads();
    // layers 1,2: 128 -> 128, ping-pong h0 <-> h1
    for (int layer = 0; layer < 2; layer++) {
        const float* hin  = (layer == 0) ? h0 : h1;
        float* hout       = (layer == 0) ? h1 : h0;
        const float4* wv = (const float4*)(layer == 0 ? d_w1v : d_w2v);
        float bv = (layer == 0) ? mb1[t] : mb2[t];
        #pragma unroll
        for (int s = 0; s < SS; s++) acc[s] = bv;
        for (int c4 = 0; c4 < 32; c4++) {
            float4 w = wv[c4 * 128 + t];
            #pragma unroll
            for (int s = 0; s < SS; s++) {
                float4 gv = *(const float4*)(hin + s * 128 + c4 * 4);
                acc[s] = fmaf(gv.x, w.x, acc[s]);
                acc[s] = fmaf(gv.y, w.y, acc[s]);
                acc[s] = fmaf(gv.z, w.z, acc[s]);
                acc[s] = fmaf(gv.w, w.w, acc[s]);
            }
        }
        __syncthreads();
        #pragma unroll
        for (int s = 0; s < SS; s++) hout[s * 128 + t] = fmaxf(acc[s], 0.f);
        __syncthreads();
    }
    // maxpool over S (final hidden is in h0)
    float m = h0[t];
    #pragma unroll
    for (int s = 1; s < SS; s++) m = fmaxf(m, h0[s * 128 + t]);
    d_nf[bp * 128 + t] = m;
    // FiLM (replicates torch repeat/chunk/reshape index scrambling)
    int pm = p & 127;
    float sc = d_ss256[b * 256 + pm] + 1.f;
    float sh = d_ss256[b * 256 + 128 + pm];
    out[OFF_NF + ((size_t)b * 128 + t) * 256 + p] = fmaf(m, sc, sh);
}

// ---- label branch: [label(18)|nf(128)] -> 3x dense+relu (256) -> FiLM ----
__global__ void __launch_bounds__(256)
k_label(const float* __restrict__ blabel,
        const float* __restrict__ lb0, const float* __restrict__ lb1,
        const float* __restrict__ lb2, float* __restrict__ out) {
    int bp = blockIdx.x;
    int b = bp >> 8, p = bp & 255;
    int t = threadIdx.x;
    __shared__ __align__(16) float li[148];
    __shared__ __align__(16) float h[256];
    if (t < 148) {
        float v = 0.f;
        if (t < NCLS) v = blabel[bp * NCLS + t];
        else if (t < NCLS + 128) v = d_nf[bp * 128 + (t - NCLS)];
        li[t] = v;
    }
    __syncthreads();
    // layer 0: 146 -> 256
    float acc = lb0[t];
    {
        const float4* wv = (const float4*)d_l0v;
        for (int c4 = 0; c4 < 37; c4++) {
            float4 w = wv[c4 * 256 + t];
            float4 gv = *(const float4*)(li + c4 * 4);
            acc = fmaf(gv.x, w.x, acc);
            acc = fmaf(gv.y, w.y, acc);
            acc = fmaf(gv.z, w.z, acc);
            acc = fmaf(gv.w, w.w, acc);
        }
    }
    h[t] = fmaxf(acc, 0.f);
    __syncthreads();
    // layer 1: 256 -> 256
    acc = lb1[t];
    {
        const float4* wv = (const float4*)d_l1v;
        for (int c4 = 0; c4 < 64; c4++) {
            float4 w = wv[c4 * 256 + t];
            float4 gv = *(const float4*)(h + c4 * 4);
            acc = fmaf(gv.x, w.x, acc);
            acc = fmaf(gv.y, w.y, acc);
            acc = fmaf(gv.z, w.z, acc);
            acc = fmaf(gv.w, w.w, acc);
        }
    }
    __syncthreads();
    h[t] = fmaxf(acc, 0.f);
    __syncthreads();
    // layer 2: 256 -> 256
    acc = lb2[t];
    {
        const float4* wv = (const float4*)d_l2v;
        for (int c4 = 0; c4 < 64; c4++) {
            float4 w = wv[c4 * 256 + t];
            float4 gv = *(const float4*)(h + c4 * 4);
            acc = fmaf(gv.x, w.x, acc);
            acc = fmaf(gv.y, w.y, acc);
            acc = fmaf(gv.z, w.z, acc);
            acc = fmaf(gv.w, w.w, acc);
        }
    }
    float val = fmaxf(acc, 0.f);
    float sc = d_ss512[b * 512 + p] + 1.f;
    float sh = d_ss512[b * 512 + 256 + p];
    out[OFF_LAB + ((size_t)b * 256 + t) * 256 + p] = fmaf(val, sc, sh);
}

extern "C" void kernel_launch(void* const* d_in, const int* in_sizes, int n_in,
                              void* d_out, int out_size) {
    const float* xyz    = (const float*)d_in[0];
    const float* feats  = (const float*)d_in[1];
    const float* bsize  = (const float*)d_in[2];
    const float* blabel = (const float*)d_in[3];
    const float* ts     = (const float*)d_in[4];
    const int*   inds   = (const int*)d_in[5];
    const float* mw0 = (const float*)d_in[6];  const float* mb0 = (const float*)d_in[7];
    const float* mw1 = (const float*)d_in[8];  const float* mb1 = (const float*)d_in[9];
    const float* mw2 = (const float*)d_in[10]; const float* mb2 = (const float*)d_in[11];
    const float* lw0 = (const float*)d_in[12]; const float* lb0 = (const float*)d_in[13];
    const float* lw1 = (const float*)d_in[14]; const float* lb1 = (const float*)d_in[15];
    const float* lw2 = (const float*)d_in[16]; const float* lb2 = (const float*)d_in[17];
    const float* tw0 = (const float*)d_in[18]; const float* tb0 = (const float*)d_in[19];
    const float* tw1 = (const float*)d_in[20]; const float* tb1 = (const float*)d_in[21];
    const float* bw  = (const float*)d_in[22]; const float* bb  = (const float*)d_in[23];
    const float* tlw0 = (const float*)d_in[24]; const float* tlb0 = (const float*)d_in[25];
    const float* tlw1 = (const float*)d_in[26]; const float* tlb1 = (const float*)d_in[27];
    const float* blw  = (const float*)d_in[28]; const float* blb  = (const float*)d_in[29];
    float* out = (float*)d_out;

    // weight transposes to vectorized [c4][o][4] layouts
    auto tg = [](int total) { return (total + 255) / 256; };
    k_transpose_vec<<<tg(65*128*4), 256>>>(mw0, 10, 128, 259, 65);
    k_transpose_vec<<<tg(32*128*4), 256>>>(mw1, 11, 128, 128, 32);
    k_transpose_vec<<<tg(32*128*4), 256>>>(mw2, 12, 128, 128, 32);
    k_transpose_vec<<<tg(37*256*4), 256>>>(lw0, 13, 256, 146, 37);
    k_transpose_vec<<<tg(64*256*4), 256>>>(lw1, 14, 256, 256, 64);
    k_transpose_vec<<<tg(64*256*4), 256>>>(lw2, 15, 256, 256, 64);

    // time-embedding branch
    k_sinusoid<<<tg(Bb*(128+256)), 256>>>(ts);
    k_dense<<<tg(Bb*512), 256>>>(0, tw0, tb0, 2, 128, 512, 0);
    k_dense<<<tg(Bb*512), 256>>>(2, tw1, tb1, 3, 512, 512, 1);
    k_dense<<<tg(Bb*256), 256>>>(3, bw,  bb,  4, 512, 256, 2);
    k_dense<<<tg(Bb*1024), 256>>>(1, tlw0, tlb0, 5, 256, 1024, 0);
    k_dense<<<tg(Bb*1024), 256>>>(5, tlw1, tlb1, 6, 1024, 1024, 1);
    k_dense<<<tg(Bb*512), 256>>>(6, blw,  blb,  7, 1024, 512, 2);

    // selection (warp per proposal)
    k_select<<<(Bb*PP*32 + 255) / 256, 256>>>(xyz, bsize, inds, out);

    // point MLP (static smem, ping-pong hidden buffers)
    k_pointmlp<<<Bb * PP, 128>>>(xyz, feats, mb0, mb1, mb2, out);

    // label branch
    k_label<<<Bb * PP, 256>>>(blabel, lb0, lb1, lb2, out);
}

// round 4
// speedup vs baseline: 1.4924x; 1.4924x over previous
#include <cuda_runtime.h>
#include <math.h>

#define Bb 8
#define NPTS 20000
#define PP 256
#define SS 32
#define CC 256
#define NCLS 18

// ---- output layout (concatenated float32) ----
#define OFF_NF   6144
#define OFF_LAB  268288
#define OFF_INDS 792576

// ---- scratch (__device__ globals; no allocation allowed) ----
__device__ float d_featT[(size_t)Bb*NPTS*CC];   // features transposed [B][N][C]
__device__ int   d_samp[Bb*PP*SS];
__device__ float d_center[Bb*PP*3];
__device__ float d_nf[Bb*PP*128];
__device__ float d_ss256[Bb*256];
__device__ float d_ss512[Bb*512];
// vectorized weights for point/label MLPs: [(c4*O+o)*4+j] = W[o][c4*4+j] (0-pad)
__device__ float d_w0v[65*128*4];
__device__ float d_w1v[32*128*4];
__device__ float d_w2v[32*128*4];
__device__ float d_l0v[37*256*4];
__device__ float d_l1v[64*256*4];
__device__ float d_l2v[64*256*4];
// transposed time-MLP weights: Wt[i*O+o] = W[o*I+i]
__device__ float d_tw0T[128*512];
__device__ float d_tw1T[512*512];
__device__ float d_bwT[512*256];
__device__ float d_tlw0T[256*1024];
__device__ float d_tlw1T[1024*1024];
__device__ float d_blwT[1024*512];

// ---- packed f32x2 helpers ----
__device__ __forceinline__ unsigned long long pack2(float x, float y) {
    unsigned long long r;
    asm("mov.b64 %0, {%1, %2};" : "=l"(r) : "f"(x), "f"(y));
    return r;
}
__device__ __forceinline__ void unpack2(unsigned long long v, float& x, float& y) {
    asm("mov.b64 {%0, %1}, %2;" : "=f"(x), "=f"(y) : "l"(v));
}
__device__ __forceinline__ void ffma2(unsigned long long& d, unsigned long long a,
                                      unsigned long long b) {
    asm("fma.rn.f32x2 %0, %1, %2, %0;" : "+l"(d) : "l"(a), "l"(b));
}

__device__ __forceinline__ float gelu_exact(float x) {
    return 0.5f * x * (1.0f + erff(x * 0.70710678118654752f));
}
__device__ __forceinline__ float silu_f(float x) {
    return x / (1.0f + expf(-x));
}

// ---- prep1: vectorize point/label MLP weights ----
__device__ __forceinline__ void vec_one(float* dst, const float* W,
                                        int O, int Cin, int i) {
    int j = i & 3, r = i >> 2;
    int o = r % O, c4 = r / O, c = c4 * 4 + j;
    dst[i] = (c < Cin) ? W[o * Cin + c] : 0.f;
}
#define S_W0 (65*128*4)
#define S_W1 (32*128*4)
#define S_L0 (37*256*4)
#define S_L1 (64*256*4)
__global__ void k_prep1(const float* __restrict__ mw0, const float* __restrict__ mw1,
                        const float* __restrict__ mw2, const float* __restrict__ lw0,
                        const float* __restrict__ lw1, const float* __restrict__ lw2) {
    int i = blockIdx.x * blockDim.x + threadIdx.x;
    int off = 0;
    if (i < off + S_W0) { vec_one(d_w0v, mw0, 128, 259, i - off); return; } off += S_W0;
    if (i < off + S_W1) { vec_one(d_w1v, mw1, 128, 128, i - off); return; } off += S_W1;
    if (i < off + S_W1) { vec_one(d_w2v, mw2, 128, 128, i - off); return; } off += S_W1;
    if (i < off + S_L0) { vec_one(d_l0v, lw0, 256, 146, i - off); return; } off += S_L0;
    if (i < off + S_L1) { vec_one(d_l1v, lw1, 256, 256, i - off); return; } off += S_L1;
    if (i < off + S_L1) { vec_one(d_l2v, lw2, 256, 256, i - off); return; }
}
#define PREP1_TOTAL (S_W0 + 2*S_W1 + S_L0 + 2*S_L1)

// ---- prep2: transpose time-MLP weights (coalesced writes) ----
__device__ __forceinline__ void tr_one(float* dst, const float* src,
                                       int I, int O, int idx) {
    int o = idx % O, i = idx / O;
    dst[idx] = src[o * I + i];
}
__global__ void k_prep2(const float* __restrict__ tw0, const float* __restrict__ tw1,
                        const float* __restrict__ bw, const float* __restrict__ tlw0,
                        const float* __restrict__ tlw1, const float* __restrict__ blw) {
    int i = blockIdx.x * blockDim.x + threadIdx.x;
    int off = 0;
    if (i < off + 128*512)   { tr_one(d_tw0T,  tw0,  128,  512,  i - off); return; } off += 128*512;
    if (i < off + 512*512)   { tr_one(d_tw1T,  tw1,  512,  512,  i - off); return; } off += 512*512;
    if (i < off + 512*256)   { tr_one(d_bwT,   bw,   512,  256,  i - off); return; } off += 512*256;
    if (i < off + 256*1024)  { tr_one(d_tlw0T, tlw0, 256,  1024, i - off); return; } off += 256*1024;
    if (i < off + 1024*1024) { tr_one(d_tlw1T, tlw1, 1024, 1024, i - off); return; } off += 1024*1024;
    if (i < off + 1024*512)  { tr_one(d_blwT,  blw,  1024, 512,  i - off); return; }
}
#define PREP2_TOTAL (128*512 + 512*512 + 512*256 + 256*1024 + 1024*1024 + 1024*512)

// ---- features transpose: [B][C][N] -> [B][N][C], tiled ----
__global__ void k_featT(const float* __restrict__ feat) {
    __shared__ float tile[32][33];
    int b = blockIdx.z;
    int n0 = blockIdx.x * 32, c0 = blockIdx.y * 32;
    int tx = threadIdx.x, ty = threadIdx.y;   // 32 x 8
    const float* src = feat + ((size_t)b * CC + c0) * NPTS + n0;
    #pragma unroll
    for (int j = 0; j < 32; j += 8) tile[ty + j][tx] = src[(size_t)(ty + j) * NPTS + tx];
    __syncthreads();
    float* dst = d_featT + ((size_t)b * NPTS + n0) * CC + c0;
    #pragma unroll
    for (int j = 0; j < 32; j += 8) dst[(size_t)(ty + j) * CC + tx] = tile[tx][ty + j];
}

// ---- fused time-MLP: one block per (chain, batch) ----
__global__ void __launch_bounds__(1024)
k_time(const float* __restrict__ ts,
       const float* __restrict__ tb0, const float* __restrict__ tb1,
       const float* __restrict__ bb,
       const float* __restrict__ tlb0, const float* __restrict__ tlb1,
       const float* __restrict__ blb) {
    int chain = blockIdx.x >> 3;
    int b = blockIdx.x & 7;
    int t = threadIdx.x;
    __shared__ float e[256];
    __shared__ float h1[1024];
    __shared__ float h2[1024];
    float tsv = ts[b];
    if (chain == 0) {
        if (t < 128) {
            int k = (t < 64) ? t : t - 64;
            float fr = expf((float)k * (float)(-9.210340371976184 / 63.0));
            float ev = tsv * fr;
            e[t] = (float)((t < 64) ? sin((double)ev) : cos((double)ev));
        }
        __syncthreads();
        if (t < 512) {
            float acc = tb0[t];
            #pragma unroll 4
            for (int i = 0; i < 128; i++) acc = fmaf(e[i], d_tw0T[i * 512 + t], acc);
            h1[t] = gelu_exact(acc);
        }
        __syncthreads();
        if (t < 512) {
            float acc = tb1[t];
            #pragma unroll 4
            for (int i = 0; i < 512; i++) acc = fmaf(h1[i], d_tw1T[i * 512 + t], acc);
            h2[t] = silu_f(acc);
        }
        __syncthreads();
        if (t < 256) {
            float acc = bb[t];
            #pragma unroll 4
            for (int i = 0; i < 512; i++) acc = fmaf(h2[i], d_bwT[i * 256 + t], acc);
            d_ss256[b * 256 + t] = acc;
        }
    } else {
        if (t < 256) {
            int k = (t < 128) ? t : t - 128;
            float fr = expf((float)k * (float)(-9.210340371976184 / 127.0));
            float ev = tsv * fr;
            e[t] = (float)((t < 128) ? sin((double)ev) : cos((double)ev));
        }
        __syncthreads();
        {
            float acc = tlb0[t];
            #pragma unroll 4
            for (int i = 0; i < 256; i++) acc = fmaf(e[i], d_tlw0T[i * 1024 + t], acc);
            h1[t] = gelu_exact(acc);
        }
        __syncthreads();
        {
            float acc = tlb1[t];
            #pragma unroll 4
            for (int i = 0; i < 1024; i++) acc = fmaf(h1[i], d_tlw1T[i * 1024 + t], acc);
            h2[t] = silu_f(acc);
        }
        __syncthreads();
        if (t < 512) {
            float acc = blb[t];
            #pragma unroll 4
            for (int i = 0; i < 1024; i++) acc = fmaf(h2[i], d_blwT[i * 512 + t], acc);
            d_ss512[b * 512 + t] = acc;
        }
    }
}

// ---- selection: warp per (b,p), 128 pts/iter (MLP=4) ----
__global__ void k_select(const float* __restrict__ xyz,
                         const float* __restrict__ bsize,
                         const int* __restrict__ inds,
                         float* __restrict__ out) {
    int gw = (blockIdx.x * blockDim.x + threadIdx.x) >> 5;
    int lane = threadIdx.x & 31;
    int wl = threadIdx.x >> 5;
    __shared__ int buf[8][SS];
    if (gw >= Bb * PP) return;
    int b = gw >> 8;
    int ind = inds[gw];
    const float* xb = xyz + (size_t)b * NPTS * 3;
    float cx = xb[ind * 3], cy = xb[ind * 3 + 1], cz = xb[ind * 3 + 2];
    float hx = bsize[gw * 3 + 0] * 0.5f;
    float hy = bsize[gw * 3 + 1] * 0.5f;
    float hz = bsize[gw * 3 + 2] * 0.5f;

    int found = 0;
    for (int base = 0; base < NPTS && found < SS; base += 128) {
        unsigned m[4];
        #pragma unroll
        for (int j = 0; j < 4; j++) {
            int i = base + j * 32 + lane;
            bool in = false;
            if (i < NPTS) {
                float x = xb[i * 3], y = xb[i * 3 + 1], z = xb[i * 3 + 2];
                in = (fabsf(x - cx) <= hx) && (fabsf(y - cy) <= hy) && (fabsf(z - cz) <= hz);
            }
            m[j] = __ballot_sync(0xffffffffu, in);
        }
        #pragma unroll
        for (int j = 0; j < 4; j++) {
            int fb = found;
            found += __popc(m[j]);
            if (fb < SS && ((m[j] >> lane) & 1u)) {
                int r = fb + __popc(m[j] & ((1u << lane) - 1u));
                if (r < SS) buf[wl][r] = base + j * 32 + lane;
            }
        }
    }
    int ce = found < SS ? found : SS;   // >= 1 (center point is always inside)
    __syncwarp();
    d_samp[gw * SS + lane] = buf[wl][lane % ce];
    if (lane < 3) {
        float cv = (lane == 0) ? cx : ((lane == 1) ? cy : cz);
        out[gw * 3 + lane] = cv;
        d_center[gw * 3 + lane] = cv;
    }
    if (lane == 0) out[OFF_INDS + gw] = (float)ind;
}

// ---- point MLP with packed f32x2 FMA; pair-major activation tile ----
#define GROWS 260
#define RS 18            // row stride in float2 (even -> 16B-aligned LDS.128)
__global__ void __launch_bounds__(128)
k_pointmlp(const float* __restrict__ xyz,
           const float* __restrict__ mb0, const float* __restrict__ mb1,
           const float* __restrict__ mb2) {
    int bp = blockIdx.x;
    int b = bp >> 8;
    int t = threadIdx.x;
    __shared__ __align__(16) float2 g2[GROWS * RS];   // 37.4 KB
    __shared__ int sidx[SS];
    __shared__ float ctr[3];
    float* gf = (float*)g2;
    if (t < SS) sidx[t] = d_samp[bp * SS + t];
    if (t < 3)  ctr[t] = d_center[bp * 3 + t];
    __syncthreads();
    if (t < 96) {
        int s = t / 3, d = t % 3;
        gf[d * (2 * RS) + s] = xyz[((size_t)b * NPTS + sidx[s]) * 3 + d] - ctr[d];
    }
    if (t < SS) gf[259 * (2 * RS) + t] = 0.f;   // zero pad row (c=259)
    {   // coalesced gather from transposed features
        int s = t >> 2, q = t & 3;
        const float4* fr = (const float4*)(d_featT + ((size_t)b * NPTS + sidx[s]) * CC);
        #pragma unroll
        for (int k = 0; k < 16; k++) {
            float4 v = fr[q + 4 * k];
            int c = 4 * (q + 4 * k);
            gf[(3 + c) * (2 * RS) + s] = v.x;
            gf[(4 + c) * (2 * RS) + s] = v.y;
            gf[(5 + c) * (2 * RS) + s] = v.z;
            gf[(6 + c) * (2 * RS) + s] = v.w;
        }
    }
    __syncthreads();

    unsigned long long acc[16];
    // layer 0: 259(+1 pad) -> 128
    {
        float bv = mb0[t];
        unsigned long long b2 = pack2(bv, bv);
        #pragma unroll
        for (int i = 0; i < 16; i++) acc[i] = b2;
        const float4* wv = (const float4*)d_w0v;
        for (int c4 = 0; c4 < 65; c4++) {
            float4 w = wv[c4 * 128 + t];
            #pragma unroll
            for (int cj = 0; cj < 4; cj++) {
                float wj = (cj == 0) ? w.x : (cj == 1) ? w.y : (cj == 2) ? w.z : w.w;
                unsigned long long wp = pack2(wj, wj);
                const ulonglong2* row = (const ulonglong2*)(g2 + (c4 * 4 + cj) * RS);
                #pragma unroll
                for (int s4 = 0; s4 < 8; s4++) {
                    ulonglong2 gg = row[s4];
                    ffma2(acc[2 * s4],     gg.x, wp);
                    ffma2(acc[2 * s4 + 1], gg.y, wp);
                }
            }
        }
    }
    __syncthreads();
    float2* h0 = g2;
    float2* h1 = g2 + 128 * RS;
    #pragma unroll
    for (int i = 0; i < 16; i++) {
        float lo, hi; unpack2(acc[i], lo, hi);
        h0[t * RS + i] = make_float2(fmaxf(lo, 0.f), fmaxf(hi, 0.f));
    }
    __syncthreads();
    // layers 1,2: 128 -> 128
    for (int layer = 0; layer < 2; layer++) {
        const float4* wv = (const float4*)(layer == 0 ? d_w1v : d_w2v);
        float bv = (layer == 0) ? mb1[t] : mb2[t];
        const float2* hin = (layer == 0) ? h0 : h1;
        unsigned long long b2 = pack2(bv, bv);
        #pragma unroll
        for (int i = 0; i < 16; i++) acc[i] = b2;
        for (int c4 = 0; c4 < 32; c4++) {
            float4 w = wv[c4 * 128 + t];
            #pragma unroll
            for (int cj = 0; cj < 4; cj++) {
                float wj = (cj == 0) ? w.x : (cj == 1) ? w.y : (cj == 2) ? w.z : w.w;
                unsigned long long wp = pack2(wj, wj);
                const ulonglong2* row = (const ulonglong2*)(hin + (c4 * 4 + cj) * RS);
                #pragma unroll
                for (int s4 = 0; s4 < 8; s4++) {
                    ulonglong2 gg = row[s4];
                    ffma2(acc[2 * s4],     gg.x, wp);
                    ffma2(acc[2 * s4 + 1], gg.y, wp);
                }
            }
        }
        __syncthreads();
        if (layer == 0) {
            #pragma unroll
            for (int i = 0; i < 16; i++) {
                float lo, hi; unpack2(acc[i], lo, hi);
                h1[t * RS + i] = make_float2(fmaxf(lo, 0.f), fmaxf(hi, 0.f));
            }
            __syncthreads();
        } else {
            // maxpool over samples (relu(max) == max(relu) since relu monotone)
            float mm = -1e30f;
            #pragma unroll
            for (int i = 0; i < 16; i++) {
                float lo, hi; unpack2(acc[i], lo, hi);
                mm = fmaxf(mm, fmaxf(lo, hi));
            }
            d_nf[bp * 128 + t] = fmaxf(mm, 0.f);
        }
    }
}

// ---- label branch + both FiLM epilogues ----
__global__ void __launch_bounds__(256)
k_label(const float* __restrict__ blabel,
        const float* __restrict__ lb0, const float* __restrict__ lb1,
        const float* __restrict__ lb2, float* __restrict__ out) {
    int bp = blockIdx.x;
    int b = bp >> 8, p = bp & 255;
    int t = threadIdx.x;
    __shared__ __align__(16) float li[148];
    __shared__ __align__(16) float h[256];
    if (t < 148) {
        float v = 0.f;
        if (t < NCLS) v = blabel[bp * NCLS + t];
        else if (t < NCLS + 128) v = d_nf[bp * 128 + (t - NCLS)];
        li[t] = v;
    }
    // new_features FiLM epilogue (torch repeat/chunk/reshape scrambling)
    if (t < 128) {
        float m = d_nf[bp * 128 + t];
        int pm = p & 127;
        float sc = d_ss256[b * 256 + pm] + 1.f;
        float sh = d_ss256[b * 256 + 128 + pm];
        out[OFF_NF + ((size_t)b * 128 + t) * 256 + p] = fmaf(m, sc, sh);
    }
    __syncthreads();
    float acc = lb0[t];
    {
        const float4* wv = (const float4*)d_l0v;
        for (int c4 = 0; c4 < 37; c4++) {
            float4 w = wv[c4 * 256 + t];
            float4 gv = *(const float4*)(li + c4 * 4);
            acc = fmaf(gv.x, w.x, acc); acc = fmaf(gv.y, w.y, acc);
            acc = fmaf(gv.z, w.z, acc); acc = fmaf(gv.w, w.w, acc);
        }
    }
    h[t] = fmaxf(acc, 0.f);
    __syncthreads();
    acc = lb1[t];
    {
        const float4* wv = (const float4*)d_l1v;
        for (int c4 = 0; c4 < 64; c4++) {
            float4 w = wv[c4 * 256 + t];
            float4 gv = *(const float4*)(h + c4 * 4);
            acc = fmaf(gv.x, w.x, acc); acc = fmaf(gv.y, w.y, acc);
            acc = fmaf(gv.z, w.z, acc); acc = fmaf(gv.w, w.w, acc);
        }
    }
    __syncthreads();
    h[t] = fmaxf(acc, 0.f);
    __syncthreads();
    acc = lb2[t];
    {
        const float4* wv = (const float4*)d_l2v;
        for (int c4 = 0; c4 < 64; c4++) {
            float4 w = wv[c4 * 256 + t];
            float4 gv = *(const float4*)(h + c4 * 4);
            acc = fmaf(gv.x, w.x, acc); acc = fmaf(gv.y, w.y, acc);
            acc = fmaf(gv.z, w.z, acc); acc = fmaf(gv.w, w.w, acc);
        }
    }
    float val = fmaxf(acc, 0.f);
    float sc = d_ss512[b * 512 + p] + 1.f;
    float sh = d_ss512[b * 512 + 256 + p];
    out[OFF_LAB + ((size_t)b * 256 + t) * 256 + p] = fmaf(val, sc, sh);
}

extern "C" void kernel_launch(void* const* d_in, const int* in_sizes, int n_in,
                              void* d_out, int out_size) {
    const float* xyz    = (const float*)d_in[0];
    const float* feats  = (const float*)d_in[1];
    const float* bsize  = (const float*)d_in[2];
    const float* blabel = (const float*)d_in[3];
    const float* ts     = (const float*)d_in[4];
    const int*   inds   = (const int*)d_in[5];
    const float* mw0 = (const float*)d_in[6];  const float* mb0 = (const float*)d_in[7];
    const float* mw1 = (const float*)d_in[8];  const float* mb1 = (const float*)d_in[9];
    const float* mw2 = (const float*)d_in[10]; const float* mb2 = (const float*)d_in[11];
    const float* lw0 = (const float*)d_in[12]; const float* lb0 = (const float*)d_in[13];
    const float* lw1 = (const float*)d_in[14]; const float* lb1 = (const float*)d_in[15];
    const float* lw2 = (const float*)d_in[16]; const float* lb2 = (const float*)d_in[17];
    const float* tw0 = (const float*)d_in[18]; const float* tb0 = (const float*)d_in[19];
    const float* tw1 = (const float*)d_in[20]; const float* tb1 = (const float*)d_in[21];
    const float* bw  = (const float*)d_in[22]; const float* bb  = (const float*)d_in[23];
    const float* tlw0 = (const float*)d_in[24]; const float* tlb0 = (const float*)d_in[25];
    const float* tlw1 = (const float*)d_in[26]; const float* tlb1 = (const float*)d_in[27];
    const float* blw  = (const float*)d_in[28]; const float* blb  = (const float*)d_in[29];
    float* out = (float*)d_out;

    k_prep1<<<(PREP1_TOTAL + 255) / 256, 256>>>(mw0, mw1, mw2, lw0, lw1, lw2);   // 0
    k_featT<<<dim3(NPTS / 32, CC / 32, Bb), dim3(32, 8)>>>(feats);               // 1
    k_prep2<<<(PREP2_TOTAL + 255) / 256, 256>>>(tw0, tw1, bw, tlw0, tlw1, blw);  // 2
    k_select<<<(Bb * PP * 32 + 255) / 256, 256>>>(xyz, bsize, inds, out);        // 3
    k_time<<<16, 1024>>>(ts, tb0, tb1, bb, tlb0, tlb1, blb);                     // 4
    k_pointmlp<<<Bb * PP, 128>>>(xyz, mb0, mb1, mb2);                            // 5 (ncu window)
    k_label<<<Bb * PP, 256>>>(blabel, lb0, lb1, lb2, out);                       // 6
}